// round 5
// baseline (speedup 1.0000x reference)
#include <cuda_runtime.h>
#include <cuda_bf16.h>
#include <math.h>
#include <stdint.h>

#define BATCH 2
#define SEQ   2048
#define DMOD  1024
#define NH    16
#define DK    64
#define MROWS (BATCH*SEQ)   // 4096

// ------------------------- global scratch (no allocs) -----------------------
__device__ __nv_bfloat16 g_Xh[MROWS*DMOD], g_Xl[MROWS*DMOD];
__device__ __nv_bfloat16 g_Wh[4*DMOD*DMOD], g_Wl[4*DMOD*DMOD];
__device__ __nv_bfloat16 g_Qh[BATCH*NH*SEQ*DK], g_Ql[BATCH*NH*SEQ*DK];
__device__ __nv_bfloat16 g_Kh[BATCH*NH*SEQ*DK], g_Kl[BATCH*NH*SEQ*DK];
__device__ __nv_bfloat16 g_Vh[BATCH*NH*SEQ*DK], g_Vl[BATCH*NH*SEQ*DK];
__device__ __nv_bfloat16 g_Oh[MROWS*DMOD], g_Ol[MROWS*DMOD];
__device__ float2 g_cs[SEQ][DK/2];   // (cos, sin) per (pos, pair)

// ------------------------------- helpers ------------------------------------
__device__ __forceinline__ void split2(float e, float o, uint32_t& hi, uint32_t& lo)
{
    __nv_bfloat16 eh = __float2bfloat16(e);
    __nv_bfloat16 oh = __float2bfloat16(o);
    float er  = e - __bfloat162float(eh);
    float orr = o - __bfloat162float(oh);
    __nv_bfloat16 el = __float2bfloat16(er);
    __nv_bfloat16 ol = __float2bfloat16(orr);
    hi = (uint32_t)__bfloat16_as_ushort(eh) | ((uint32_t)__bfloat16_as_ushort(oh) << 16);
    lo = (uint32_t)__bfloat16_as_ushort(el) | ((uint32_t)__bfloat16_as_ushort(ol) << 16);
}

__device__ __forceinline__ void mma16816(float* c, const uint32_t* a, const uint32_t* b)
{
    asm volatile(
        "mma.sync.aligned.m16n8k16.row.col.f32.bf16.bf16.f32 "
        "{%0,%1,%2,%3}, {%4,%5,%6,%7}, {%8,%9}, {%0,%1,%2,%3};\n"
        : "+f"(c[0]), "+f"(c[1]), "+f"(c[2]), "+f"(c[3])
        : "r"(a[0]), "r"(a[1]), "r"(a[2]), "r"(a[3]), "r"(b[0]), "r"(b[1]));
}

__device__ __forceinline__ void ldsm_x4(uint32_t* r, uint32_t addr)
{
    asm volatile("ldmatrix.sync.aligned.m8n8.x4.shared.b16 {%0,%1,%2,%3}, [%4];"
                 : "=r"(r[0]), "=r"(r[1]), "=r"(r[2]), "=r"(r[3]) : "r"(addr));
}
__device__ __forceinline__ void ldsm_x4_t(uint32_t* r, uint32_t addr)
{
    asm volatile("ldmatrix.sync.aligned.m8n8.x4.trans.shared.b16 {%0,%1,%2,%3}, [%4];"
                 : "=r"(r[0]), "=r"(r[1]), "=r"(r[2]), "=r"(r[3]) : "r"(addr));
}
__device__ __forceinline__ void cpa16(uint32_t dst, const void* src)
{
    asm volatile("cp.async.cg.shared.global [%0], [%1], 16;" :: "r"(dst), "l"(src));
}
template<int N> __device__ __forceinline__ void cp_wait()
{
    asm volatile("cp.async.wait_group %0;" :: "n"(N));
}

// -------------------------- prep kernels ------------------------------------
__global__ void rope_table_kernel()
{
    int idx = blockIdx.x * blockDim.x + threadIdx.x;      // SEQ*32
    int s = idx >> 5, j = idx & 31;
    float invf = powf(10000.0f, -(float)(2 * j) / 64.0f);
    float ang = (float)s * invf;
    float sn, cs;
    sincosf(ang, &sn, &cs);
    g_cs[s][j] = make_float2(cs, sn);
}

__global__ void split_kernel(const float* __restrict__ src, int sel, int n4)
{
    int i = blockIdx.x * blockDim.x + threadIdx.x;
    if (i >= n4) return;
    __nv_bfloat16 *h, *l;
    if (sel == 0) { h = g_Xh; l = g_Xl; }
    else { h = g_Wh + (size_t)(sel - 1) * DMOD * DMOD;
           l = g_Wl + (size_t)(sel - 1) * DMOD * DMOD; }
    float4 v = ((const float4*)src)[i];
    uint32_t h0, l0, h1, l1;
    split2(v.x, v.y, h0, l0);
    split2(v.z, v.w, h1, l1);
    *(uint32_t*)&h[4 * i]     = h0;
    *(uint32_t*)&h[4 * i + 2] = h1;
    *(uint32_t*)&l[4 * i]     = l0;
    *(uint32_t*)&l[4 * i + 2] = l1;
}

// ---------------------------------------------------------------------------
// Tensor-core GEMM (3xBF16 split, pre-split inputs): C = A @ W^T
// BM=128, BN=64, BK=32, 256 threads, 8 warps (4x2), warp tile 32x32.
// mode 0: +RoPE -> Qh/Ql   1: +RoPE -> Kh/Kl   2: -> Vh/Vl   3: A=O -> out fp32
// ---------------------------------------------------------------------------
__global__ __launch_bounds__(256) void gemm_mma_kernel(int widx, int mode,
                                                       float* __restrict__ out)
{
    const __nv_bfloat16* Ah = (mode == 3) ? g_Oh : g_Xh;
    const __nv_bfloat16* Al = (mode == 3) ? g_Ol : g_Xl;
    const __nv_bfloat16* Wh = g_Wh + (size_t)widx * DMOD * DMOD;
    const __nv_bfloat16* Wl = g_Wl + (size_t)widx * DMOD * DMOD;

    __shared__ uint32_t sAh[16][136], sAl[16][136];
    __shared__ uint32_t sBh[16][72],  sBl[16][72];

    const int tid  = threadIdx.x;
    const int warp = tid >> 5, lane = tid & 31;
    const int g = lane >> 2, t = lane & 3;
    const int wr = warp >> 1, wc = warp & 1;
    const int m0 = blockIdx.y * 128;
    const int n0 = blockIdx.x * 64;

    float acc[2][4][4];
#pragma unroll
    for (int mt = 0; mt < 2; mt++)
#pragma unroll
        for (int nt = 0; nt < 4; nt++)
#pragma unroll
            for (int i = 0; i < 4; i++) acc[mt][nt][i] = 0.f;

    // global->reg preload indices
    int arow[2], akq[2];
#pragma unroll
    for (int i = 0; i < 2; i++) {
        int lin = tid + 256 * i;
        arow[i] = lin & 127;
        akq[i]  = lin >> 7;     // 0..3 (uint4 within row)
    }
    const int brow = tid & 63, bkq = tid >> 6;

    uint4 rAh[2], rAl[2], rBh, rBl;
#pragma unroll
    for (int i = 0; i < 2; i++) {
        rAh[i] = *(const uint4*)&Ah[(size_t)(m0 + arow[i]) * DMOD + akq[i] * 8];
        rAl[i] = *(const uint4*)&Al[(size_t)(m0 + arow[i]) * DMOD + akq[i] * 8];
    }
    rBh = *(const uint4*)&Wh[(size_t)(n0 + brow) * DMOD + bkq * 8];
    rBl = *(const uint4*)&Wl[(size_t)(n0 + brow) * DMOD + bkq * 8];

    for (int k0 = 0; k0 < DMOD; k0 += 32) {
        __syncthreads();
#pragma unroll
        for (int i = 0; i < 2; i++) {
            int kp = akq[i] * 4, r = arow[i];
            sAh[kp + 0][r] = rAh[i].x; sAh[kp + 1][r] = rAh[i].y;
            sAh[kp + 2][r] = rAh[i].z; sAh[kp + 3][r] = rAh[i].w;
            sAl[kp + 0][r] = rAl[i].x; sAl[kp + 1][r] = rAl[i].y;
            sAl[kp + 2][r] = rAl[i].z; sAl[kp + 3][r] = rAl[i].w;
        }
        {
            int kp = bkq * 4;
            sBh[kp + 0][brow] = rBh.x; sBh[kp + 1][brow] = rBh.y;
            sBh[kp + 2][brow] = rBh.z; sBh[kp + 3][brow] = rBh.w;
            sBl[kp + 0][brow] = rBl.x; sBl[kp + 1][brow] = rBl.y;
            sBl[kp + 2][brow] = rBl.z; sBl[kp + 3][brow] = rBl.w;
        }
        __syncthreads();

        if (k0 + 32 < DMOD) {
            int kn = k0 + 32;
#pragma unroll
            for (int i = 0; i < 2; i++) {
                rAh[i] = *(const uint4*)&Ah[(size_t)(m0 + arow[i]) * DMOD + kn + akq[i] * 8];
                rAl[i] = *(const uint4*)&Al[(size_t)(m0 + arow[i]) * DMOD + kn + akq[i] * 8];
            }
            rBh = *(const uint4*)&Wh[(size_t)(n0 + brow) * DMOD + kn + bkq * 8];
            rBl = *(const uint4*)&Wl[(size_t)(n0 + brow) * DMOD + kn + bkq * 8];
        }

#pragma unroll
        for (int s = 0; s < 2; s++) {
            const int kr = s * 8 + t;
            uint32_t ah[2][4], al[2][4], bh[4][2], bl[4][2];
#pragma unroll
            for (int mt = 0; mt < 2; mt++) {
                int mc = wr * 32 + mt * 16 + g;
                ah[mt][0] = sAh[kr][mc];     ah[mt][1] = sAh[kr][mc + 8];
                ah[mt][2] = sAh[kr + 4][mc]; ah[mt][3] = sAh[kr + 4][mc + 8];
                al[mt][0] = sAl[kr][mc];     al[mt][1] = sAl[kr][mc + 8];
                al[mt][2] = sAl[kr + 4][mc]; al[mt][3] = sAl[kr + 4][mc + 8];
            }
#pragma unroll
            for (int nt = 0; nt < 4; nt++) {
                int nc = wc * 32 + nt * 8 + g;
                bh[nt][0] = sBh[kr][nc]; bh[nt][1] = sBh[kr + 4][nc];
                bl[nt][0] = sBl[kr][nc]; bl[nt][1] = sBl[kr + 4][nc];
            }
#pragma unroll
            for (int mt = 0; mt < 2; mt++)
#pragma unroll
                for (int nt = 0; nt < 4; nt++) {
                    mma16816(acc[mt][nt], al[mt], bh[nt]);
                    mma16816(acc[mt][nt], ah[mt], bl[nt]);
                    mma16816(acc[mt][nt], ah[mt], bh[nt]);
                }
        }
    }

    // ------------------------------- epilogue -------------------------------
#pragma unroll
    for (int mt = 0; mt < 2; mt++) {
#pragma unroll
        for (int rh = 0; rh < 2; rh++) {
            int m  = m0 + wr * 32 + mt * 16 + g + rh * 8;
            int bb = m >> 11;
            int ss = m & (SEQ - 1);
#pragma unroll
            for (int nt = 0; nt < 4; nt++) {
                float c0 = acc[mt][nt][rh * 2 + 0];
                float c1 = acc[mt][nt][rh * 2 + 1];
                int n = n0 + wc * 32 + nt * 8 + t * 2;
                if (mode == 3) {
                    *(float2*)&out[(size_t)m * DMOD + n] = make_float2(c0, c1);
                } else {
                    int h = n >> 6, i0 = n & 63;
                    size_t idx = (((size_t)(bb * NH + h)) * SEQ + ss) * DK + i0;
                    uint32_t hi, lo;
                    if (mode == 2) {
                        split2(c0, c1, hi, lo);
                        *(uint32_t*)&g_Vh[idx] = hi;
                        *(uint32_t*)&g_Vl[idx] = lo;
                    } else {
                        float2 cssn = g_cs[ss][i0 >> 1];
                        float r0 = c0 * cssn.x - c1 * cssn.y;
                        float r1 = c1 * cssn.x + c0 * cssn.y;
                        split2(r0, r1, hi, lo);
                        if (mode == 0) {
                            *(uint32_t*)&g_Qh[idx] = hi;
                            *(uint32_t*)&g_Ql[idx] = lo;
                        } else {
                            *(uint32_t*)&g_Kh[idx] = hi;
                            *(uint32_t*)&g_Kl[idx] = lo;
                        }
                    }
                }
            }
        }
    }
}

// ---------------------------------------------------------------------------
// MMA flash attention, pre-split bf16 inputs, cp.async double-buffered K/V.
// CTA: 64 queries, 4 warps. grid = (SEQ/64, BATCH*NH), block = 128.
// smem stage: Kh|Kl|Vh|Vl tiles, 64 rows x 64 cols bf16, pitch 72 (144B).
// ---------------------------------------------------------------------------
#define TPITCH 144                    // bytes per smem row
#define TILE_B (64*TPITCH)            // 9216 B per tile
#define STAGE_B (4*TILE_B)            // 36864 B per stage

__global__ __launch_bounds__(128) void attn_mma_kernel()
{
    extern __shared__ char smem[];
    const uint32_t smemB = (uint32_t)__cvta_generic_to_shared(smem);

    const int tid  = threadIdx.x;
    const int w    = tid >> 5;
    const int lane = tid & 31;
    const int g = lane >> 2, t = lane & 3;
    const int qt = (int)gridDim.x - 1 - (int)blockIdx.x;   // heavy blocks first
    const int bh = blockIdx.y;
    const int q0 = qt * 64;

    const size_t hb = (size_t)bh * SEQ * DK;
    const __nv_bfloat16* kv_src[4] = {g_Kh + hb, g_Kl + hb, g_Vh + hb, g_Vl + hb};

    // --- Q fragments (direct bf16-pair loads) ---
    uint32_t qh[4][4], ql[4][4];
    {
        const __nv_bfloat16* qh0 = g_Qh + hb + (size_t)(q0 + w * 16 + g) * DK;
        const __nv_bfloat16* ql0 = g_Ql + hb + (size_t)(q0 + w * 16 + g) * DK;
#pragma unroll
        for (int ks = 0; ks < 4; ks++) {
            int c = ks * 16 + 2 * t;
            qh[ks][0] = *(const uint32_t*)&qh0[c];
            qh[ks][1] = *(const uint32_t*)&qh0[8 * DK + c];
            qh[ks][2] = *(const uint32_t*)&qh0[c + 8];
            qh[ks][3] = *(const uint32_t*)&qh0[8 * DK + c + 8];
            ql[ks][0] = *(const uint32_t*)&ql0[c];
            ql[ks][1] = *(const uint32_t*)&ql0[8 * DK + c];
            ql[ks][2] = *(const uint32_t*)&ql0[c + 8];
            ql[ks][3] = *(const uint32_t*)&ql0[8 * DK + c + 8];
        }
    }

    // per-lane partial offsets for ldmatrix.x4
    const uint32_t kPart = (uint32_t)((lane & 7) * TPITCH + (lane >> 3) * 16);
    const uint32_t vPart = (uint32_t)(((lane & 7) + 8 * ((lane >> 3) & 1)) * TPITCH
                                      + (lane >> 4) * 16);

    auto issue = [&](int kt, int stg) {
        uint32_t base = smemB + stg * STAGE_B;
#pragma unroll
        for (int a = 0; a < 4; a++) {
            const __nv_bfloat16* s = kv_src[a] + (size_t)kt * 64 * DK;
#pragma unroll
            for (int i = 0; i < 4; i++) {
                int c = tid + i * 128;                  // 0..511
                cpa16(base + a * TILE_B + (c >> 3) * TPITCH + (c & 7) * 16,
                      s + (c >> 3) * DK + (c & 7) * 8);
            }
        }
        asm volatile("cp.async.commit_group;\n" ::);
    };

    float oacc[8][4];
#pragma unroll
    for (int nt = 0; nt < 8; nt++)
#pragma unroll
        for (int i = 0; i < 4; i++) oacc[nt][i] = 0.f;
    float mrow[2] = {-1e30f, -1e30f};
    float lrow[2] = {0.f, 0.f};

    issue(0, 0);

    for (int kt = 0; kt <= qt; kt++) {
        const int stg = kt & 1;
        if (kt < qt) { issue(kt + 1, stg ^ 1); cp_wait<1>(); }
        else         { cp_wait<0>(); }
        __syncthreads();

        const uint32_t khB = smemB + stg * STAGE_B;
        const uint32_t klB = khB + TILE_B;
        const uint32_t vhB = khB + 2 * TILE_B;
        const uint32_t vlB = khB + 3 * TILE_B;

        // --- S = Q K^T ---
        float sacc[8][4];
#pragma unroll
        for (int nt = 0; nt < 8; nt++) {
#pragma unroll
            for (int i = 0; i < 4; i++) sacc[nt][i] = 0.f;
#pragma unroll
            for (int ks2 = 0; ks2 < 2; ks2++) {
                uint32_t bh4[4], bl4[4];
                uint32_t off = (uint32_t)(nt * 8 * TPITCH + ks2 * 64) + kPart;
                ldsm_x4(bh4, khB + off);
                ldsm_x4(bl4, klB + off);
                mma16816(sacc[nt], ql[2 * ks2],     bh4 + 0);
                mma16816(sacc[nt], qh[2 * ks2],     bl4 + 0);
                mma16816(sacc[nt], qh[2 * ks2],     bh4 + 0);
                mma16816(sacc[nt], ql[2 * ks2 + 1], bh4 + 2);
                mma16816(sacc[nt], qh[2 * ks2 + 1], bl4 + 2);
                mma16816(sacc[nt], qh[2 * ks2 + 1], bh4 + 2);
            }
        }

#pragma unroll
        for (int nt = 0; nt < 8; nt++)
#pragma unroll
            for (int i = 0; i < 4; i++) sacc[nt][i] *= 0.125f;
        if (kt == qt) {
#pragma unroll
            for (int nt = 0; nt < 8; nt++)
#pragma unroll
                for (int i = 0; i < 4; i++) {
                    int col = nt * 8 + 2 * t + (i & 1);
                    int row = w * 16 + g + 8 * (i >> 1);
                    if (col > row) sacc[nt][i] = -1e30f;
                }
        }

        // --- online softmax ---
#pragma unroll
        for (int r = 0; r < 2; r++) {
            float mx = -1e30f;
#pragma unroll
            for (int nt = 0; nt < 8; nt++) {
                mx = fmaxf(mx, sacc[nt][2 * r]);
                mx = fmaxf(mx, sacc[nt][2 * r + 1]);
            }
            mx = fmaxf(mx, __shfl_xor_sync(0xffffffffu, mx, 1));
            mx = fmaxf(mx, __shfl_xor_sync(0xffffffffu, mx, 2));
            float mnew = fmaxf(mrow[r], mx);
            float corr = __expf(mrow[r] - mnew);
            mrow[r] = mnew;
            float rs = 0.f;
#pragma unroll
            for (int nt = 0; nt < 8; nt++) {
                float p0 = __expf(sacc[nt][2 * r]     - mnew);
                float p1 = __expf(sacc[nt][2 * r + 1] - mnew);
                sacc[nt][2 * r] = p0; sacc[nt][2 * r + 1] = p1;
                rs += p0 + p1;
            }
            rs += __shfl_xor_sync(0xffffffffu, rs, 1);
            rs += __shfl_xor_sync(0xffffffffu, rs, 2);
            lrow[r] = lrow[r] * corr + rs;
#pragma unroll
            for (int nt = 0; nt < 8; nt++) {
                oacc[nt][2 * r]     *= corr;
                oacc[nt][2 * r + 1] *= corr;
            }
        }

        // --- O += P V ---
#pragma unroll
        for (int kc = 0; kc < 4; kc++) {
            uint32_t pah[4], pal[4];
            split2(sacc[2 * kc][0],     sacc[2 * kc][1],     pah[0], pal[0]);
            split2(sacc[2 * kc][2],     sacc[2 * kc][3],     pah[1], pal[1]);
            split2(sacc[2 * kc + 1][0], sacc[2 * kc + 1][1], pah[2], pal[2]);
            split2(sacc[2 * kc + 1][2], sacc[2 * kc + 1][3], pah[3], pal[3]);
#pragma unroll
            for (int nt2 = 0; nt2 < 4; nt2++) {
                uint32_t vh4[4], vl4[4];
                uint32_t off = (uint32_t)(kc * 16 * TPITCH + nt2 * 32) + vPart;
                ldsm_x4_t(vh4, vhB + off);
                ldsm_x4_t(vl4, vlB + off);
                mma16816(oacc[2 * nt2],     pah, vh4 + 0);
                mma16816(oacc[2 * nt2],     pah, vl4 + 0);
                mma16816(oacc[2 * nt2],     pal, vh4 + 0);
                mma16816(oacc[2 * nt2 + 1], pah, vh4 + 2);
                mma16816(oacc[2 * nt2 + 1], pah, vl4 + 2);
                mma16816(oacc[2 * nt2 + 1], pal, vh4 + 2);
            }
        }
        __syncthreads();
    }

    // --- epilogue: write split O ---
    const int bb = bh >> 4;
    const int h  = bh & 15;
#pragma unroll
    for (int r = 0; r < 2; r++) {
        float inv = 1.f / lrow[r];
        int q = q0 + w * 16 + g + 8 * r;
        size_t rowoff = ((size_t)(bb * SEQ + q)) * DMOD + h * DK;
#pragma unroll
        for (int nt = 0; nt < 8; nt++) {
            uint32_t hi, lo;
            split2(oacc[nt][2 * r] * inv, oacc[nt][2 * r + 1] * inv, hi, lo);
            *(uint32_t*)&g_Oh[rowoff + nt * 8 + 2 * t] = hi;
            *(uint32_t*)&g_Ol[rowoff + nt * 8 + 2 * t] = lo;
        }
    }
}

// ---------------------------------------------------------------------------
extern "C" void kernel_launch(void* const* d_in, const int* in_sizes, int n_in,
                              void* d_out, int out_size)
{
    const float* X  = (const float*)d_in[0];
    const float* Wq = (const float*)d_in[1];
    const float* Wk = (const float*)d_in[2];
    const float* Wv = (const float*)d_in[3];
    const float* Wo = (const float*)d_in[4];
    float* out = (float*)d_out;

    rope_table_kernel<<<SEQ * 32 / 256, 256>>>();
    split_kernel<<<MROWS * DMOD / 4 / 256, 256>>>(X,  0, MROWS * DMOD / 4);
    split_kernel<<<DMOD * DMOD / 4 / 256, 256>>>(Wq, 1, DMOD * DMOD / 4);
    split_kernel<<<DMOD * DMOD / 4 / 256, 256>>>(Wk, 2, DMOD * DMOD / 4);
    split_kernel<<<DMOD * DMOD / 4 / 256, 256>>>(Wv, 3, DMOD * DMOD / 4);
    split_kernel<<<DMOD * DMOD / 4 / 256, 256>>>(Wo, 4, DMOD * DMOD / 4);

    dim3 ggrid(DMOD / 64, MROWS / 128);   // (16, 32)
    gemm_mma_kernel<<<ggrid, 256>>>(0, 0, nullptr);
    gemm_mma_kernel<<<ggrid, 256>>>(1, 1, nullptr);
    gemm_mma_kernel<<<ggrid, 256>>>(2, 2, nullptr);

    cudaFuncSetAttribute(attn_mma_kernel,
                         cudaFuncAttributeMaxDynamicSharedMemorySize, 2 * STAGE_B);
    attn_mma_kernel<<<dim3(SEQ / 64, BATCH * NH), 128, 2 * STAGE_B>>>();

    gemm_mma_kernel<<<ggrid, 256>>>(3, 3, out);
}